// round 16
// baseline (speedup 1.0000x reference)
#include <cuda_runtime.h>
#include <cuda_fp16.h>
#include <cstdint>

#define BB 4
#define SS 2048
#define DD 1024
#define MM (BB * SS)

// ---------------- scratch (device globals; allocation-free) ----------------
__device__ __half g_inq_h[(size_t)MM * DD], g_inq_l[(size_t)MM * DD];
__device__ __half g_ink_h[(size_t)MM * DD], g_ink_l[(size_t)MM * DD];
__device__ __half g_inv_h[(size_t)MM * DD], g_inv_l[(size_t)MM * DD];
__device__ __half g_wq_h[(size_t)DD * DD],  g_wq_l[(size_t)DD * DD];
__device__ __half g_wk_h[(size_t)DD * DD],  g_wk_l[(size_t)DD * DD];
__device__ __half g_wv_h[(size_t)DD * DD],  g_wv_l[(size_t)DD * DD];
__device__ __half g_wd_h[(size_t)DD * DD],  g_wd_l[(size_t)DD * DD];
__device__ __half g_q_h[(size_t)MM * DD],   g_q_l[(size_t)MM * DD];
__device__ __half g_k_h[(size_t)MM * DD],   g_k_l[(size_t)MM * DD];
__device__ __half g_vt_h[(size_t)MM * DD];
__device__ __half g_s_h[(size_t)BB * SS * SS];
__device__ __half g_att_h[(size_t)MM * DD];
__device__ float g_s[(size_t)BB * SS * SS];

// ---------------- asm helpers ----------------
#define MMA16816(d, a, b) \
    asm volatile("mma.sync.aligned.m16n8k16.row.col.f32.f16.f16.f32 " \
                 "{%0,%1,%2,%3}, {%4,%5,%6,%7}, {%8,%9}, {%0,%1,%2,%3};" \
                 : "+f"((d)[0]), "+f"((d)[1]), "+f"((d)[2]), "+f"((d)[3]) \
                 : "r"((a)[0]), "r"((a)[1]), "r"((a)[2]), "r"((a)[3]), \
                   "r"((b)[0]), "r"((b)[1]))

#define LDSM4(r0, r1, r2, r3, addr) \
    asm volatile("ldmatrix.sync.aligned.m8n8.x4.shared.b16 {%0,%1,%2,%3}, [%4];" \
                 : "=r"(r0), "=r"(r1), "=r"(r2), "=r"(r3) : "r"(addr))

#define CPA16(dst, src) \
    asm volatile("cp.async.cg.shared.global [%0], [%1], 16;" \
                 :: "r"(dst), "l"(src) : "memory")
#define CPA_COMMIT() asm volatile("cp.async.commit_group;" ::: "memory")

template <int N>
__device__ __forceinline__ void cpa_wait() {
    asm volatile("cp.async.wait_group %0;" :: "n"(N) : "memory");
}

__device__ __forceinline__ uint32_t smem_u32(const void* p) {
    uint32_t a;
    asm("{ .reg .u64 t; cvta.to.shared.u64 t, %1; cvt.u32.u64 %0, t; }"
        : "=r"(a) : "l"(p));
    return a;
}
__device__ __forceinline__ uint32_t sw_addr(uint32_t plane, int row, int c) {
    return plane + (uint32_t)((row * 4 + (c ^ ((row >> 1) & 3))) * 16);
}

// ---------------------------------------------------------------------------
// fp16-split tensor GEMM body (pre-split hi/lo operand planes).
// 128x128x32 tile, 256 threads (8 warps 2x4, warp tile 64x32),
// cp.async NSTAGE-deep pipeline, ldmatrix.  [2 CTAs/SM]
// NPROD==3: C += Ah*Bh + Ah*Bl + Al*Bh   (planes: Ah,Al,Bh,Bl)
// NPROD==2: C += Ah*Bh + Ah*Bl           (planes: Ah,Bh,Bl)
// NPROD==1: C += Ah*Bh                   (planes: Ah,Bh)
// OMODE 0: fp32 out. OMODE 1: hi+lo fp16 out. OMODE 2: hi-only fp16 out.
// BMODE 0: none. 1: bias per column (bias[n]). 2: bias per row (bias[m]).
// ---------------------------------------------------------------------------
template <int OMODE, int BMODE, int NPROD, int NSTAGE>
__device__ __forceinline__ void
hgemm_body(const __half* __restrict__ Ahi, const __half* __restrict__ Alo,
           const __half* __restrict__ Bhi, const __half* __restrict__ Blo,
           const float* __restrict__ bias,
           float* __restrict__ Cf, __half* __restrict__ Chi, __half* __restrict__ Clo,
           int M, int N, int K, char* smem)
{
    constexpr int PLANE   = 8192;                    // 128 rows * 64B
    constexpr int NPLANES = (NPROD == 3) ? 4 : ((NPROD == 2) ? 3 : 2);
    constexpr int STAGE   = NPLANES * PLANE;
    const uint32_t sbase  = smem_u32(smem);

    const int bm = blockIdx.y * 128;
    const int bn = blockIdx.x * 128;
    const int t    = threadIdx.x;
    const int lane = t & 31;
    const int wid  = t >> 5;
    const int widM = wid & 1;
    const int widN = wid >> 1;
    const int g  = lane >> 2;
    const int qq = lane & 3;
    const int l7   = lane & 7;
    const int lsel = (lane >> 3) & 1;
    const int lch  = lane >> 4;

    const int cr = t >> 2;    // 0..63
    const int cc = t & 3;     // 16B chunk in 64B row

    const __half* srcb[NPLANES];
    if (NPROD == 3) {
        srcb[0] = Ahi + (long long)bm * K;
        srcb[1] = Alo + (long long)bm * K;
        srcb[2] = Bhi + (long long)bn * K;
        srcb[3] = Blo + (long long)bn * K;
    } else if (NPROD == 2) {
        srcb[0] = Ahi + (long long)bm * K;
        srcb[1] = Bhi + (long long)bn * K;
        srcb[2] = Blo + (long long)bn * K;
    } else {
        srcb[0] = Ahi + (long long)bm * K;
        srcb[1] = Bhi + (long long)bn * K;
    }

    auto issue = [&](int kt, int slot) {
        const uint32_t dstb = sbase + (uint32_t)slot * STAGE;
        const long long koff = (long long)kt * 32 + cc * 8;
#pragma unroll
        for (int i = 0; i < 2 * NPLANES; ++i) {
            const int p = i >> 1;
            const int r = (i & 1) * 64 + cr;
            CPA16(sw_addr(dstb + p * PLANE, r, cc), srcb[p] + (long long)r * K + koff);
        }
    };

    float acc[4][4][4];
#pragma unroll
    for (int i = 0; i < 4; i++)
#pragma unroll
        for (int j = 0; j < 4; j++)
#pragma unroll
            for (int r = 0; r < 4; r++) acc[i][j][r] = 0.0f;

    const int nIter = K >> 5;
    const int m0 = widM * 64;
    const int n0 = widN * 32;

#pragma unroll
    for (int pre = 0; pre < NSTAGE - 1; ++pre) {
        issue(pre, pre);
        CPA_COMMIT();
    }

    for (int it = 0; it < nIter; ++it) {
        cpa_wait<NSTAGE - 2>();
        __syncthreads();
        if (it + NSTAGE - 1 < nIter) issue(it + NSTAGE - 1, (it + NSTAGE - 1) % NSTAGE);
        CPA_COMMIT();

        const uint32_t stb  = sbase + (uint32_t)(it % NSTAGE) * STAGE;
        const uint32_t pAhi = stb;
        const uint32_t pAlo = (NPROD == 3) ? stb + PLANE : 0;
        const uint32_t pBhi = stb + (NPROD == 3 ? 2 : 1) * PLANE;
        const uint32_t pBlo = (NPROD >= 2) ? stb + (NPROD == 3 ? 3 : 2) * PLANE : 0;

#pragma unroll
        for (int kk = 0; kk < 2; ++kk) {
            const int c = 2 * kk + lch;
            uint32_t bh[4][2], bl[4][2];
#pragma unroll
            for (int np = 0; np < 2; ++np) {
                const int row = n0 + np * 16 + l7 + lsel * 8;
                uint32_t r0, r1, r2, r3;
                LDSM4(r0, r1, r2, r3, sw_addr(pBhi, row, c));
                bh[np * 2][0] = r0; bh[np * 2][1] = r2;
                bh[np * 2 + 1][0] = r1; bh[np * 2 + 1][1] = r3;
                if (NPROD >= 2) {
                    LDSM4(r0, r1, r2, r3, sw_addr(pBlo, row, c));
                    bl[np * 2][0] = r0; bl[np * 2][1] = r2;
                    bl[np * 2 + 1][0] = r1; bl[np * 2 + 1][1] = r3;
                }
            }
#pragma unroll
            for (int mt = 0; mt < 4; ++mt) {
                const int row = m0 + mt * 16 + l7 + lsel * 8;
                uint32_t ah[4], al[4];
                LDSM4(ah[0], ah[1], ah[2], ah[3], sw_addr(pAhi, row, c));
                if (NPROD == 3)
                    LDSM4(al[0], al[1], al[2], al[3], sw_addr(pAlo, row, c));
#pragma unroll
                for (int nt = 0; nt < 4; ++nt) {
                    MMA16816(acc[mt][nt], ah, bh[nt]);
                    if (NPROD >= 2) MMA16816(acc[mt][nt], ah, bl[nt]);
                    if (NPROD == 3) MMA16816(acc[mt][nt], al, bh[nt]);
                }
            }
        }
    }

    // ---- epilogue ----
#pragma unroll
    for (int nt = 0; nt < 4; ++nt) {
        const int col = bn + n0 + nt * 8 + 2 * qq;
        float b0 = 0.f, b1 = 0.f;
        if (BMODE == 1) { b0 = bias[col]; b1 = bias[col + 1]; }
#pragma unroll
        for (int mt = 0; mt < 4; ++mt) {
            const int row0 = bm + m0 + mt * 16 + g;
            float r0b = b0, r1b = b1, r2b = b0, r3b = b1;
            if (BMODE == 2) {
                const float brow0 = bias[row0];
                const float brow1 = bias[row0 + 8];
                r0b = brow0; r1b = brow0; r2b = brow1; r3b = brow1;
            }
            const float v0 = acc[mt][nt][0] + r0b, v1 = acc[mt][nt][1] + r1b;
            const float v2 = acc[mt][nt][2] + r2b, v3 = acc[mt][nt][3] + r3b;
            if (OMODE == 0) {
                *(float2*)(Cf + (long long)row0 * N + col)       = make_float2(v0, v1);
                *(float2*)(Cf + (long long)(row0 + 8) * N + col) = make_float2(v2, v3);
            } else {
                __half2 h0 = __floats2half2_rn(v0, v1);
                __half2 h1 = __floats2half2_rn(v2, v3);
                *(__half2*)(Chi + (long long)row0 * N + col)       = h0;
                *(__half2*)(Chi + (long long)(row0 + 8) * N + col) = h1;
                if (OMODE == 1) {
                    float2 f0 = __half22float2(h0);
                    float2 f1 = __half22float2(h1);
                    __half2 l0 = __floats2half2_rn(v0 - f0.x, v1 - f0.y);
                    __half2 l1 = __floats2half2_rn(v2 - f1.x, v3 - f1.y);
                    *(__half2*)(Clo + (long long)row0 * N + col)       = l0;
                    *(__half2*)(Clo + (long long)(row0 + 8) * N + col) = l1;
                }
            }
        }
    }
}

// Generic wrapper: batch offsets via blockIdx.z (sA=0 shares A across batches)
template <int OMODE, int BMODE, int NPROD, int NSTAGE>
__global__ void __launch_bounds__(256, 2)
hgemm_kernel(const __half* __restrict__ Ahi, const __half* __restrict__ Alo,
             const __half* __restrict__ Bhi, const __half* __restrict__ Blo,
             const float* __restrict__ bias,
             float* __restrict__ Cf, __half* __restrict__ Chi, __half* __restrict__ Clo,
             int M, int N, int K,
             long long sA, long long sB, long long sC)
{
    extern __shared__ char smem[];
    const long long zo = (long long)blockIdx.z;
    hgemm_body<OMODE, BMODE, NPROD, NSTAGE>(
        Ahi + zo * sA, (NPROD == 3) ? Alo + zo * sA : nullptr,
        Bhi + zo * sB, (NPROD >= 2) ? Blo + zo * sB : nullptr,
        bias,
        (OMODE == 0) ? Cf + zo * sC : nullptr,
        (OMODE != 0) ? Chi + zo * sC : nullptr,
        (OMODE == 1) ? Clo + zo * sC : nullptr,
        M, N, K, smem);
}

// Fused q/k projection: blockIdx.z selects operand set (wave packing)
struct QKArgs {
    const __half *Ah[2], *Al[2], *Bh[2], *Bl[2];
    const float* bias[2];
    __half *Ch[2], *Cl[2];
};
__global__ void __launch_bounds__(256, 2)
hgemm_qk_kernel(QKArgs a, int M, int N, int K)
{
    extern __shared__ char smem[];
    const int z = blockIdx.z;
    hgemm_body<1, 1, 3, 3>(a.Ah[z], a.Al[z], a.Bh[z], a.Bl[z], a.bias[z],
                           nullptr, a.Ch[z], a.Cl[z], M, N, K, smem);
}

// ---------------------------------------------------------------------------
// fp32 -> hi/lo fp16 planes (elementwise, float4 granularity)
// ---------------------------------------------------------------------------
__global__ void __launch_bounds__(256)
convert_kernel(const float* __restrict__ in, __half* __restrict__ hi,
               __half* __restrict__ lo, size_t n4)
{
    size_t i = (size_t)blockIdx.x * blockDim.x + threadIdx.x;
    if (i >= n4) return;
    float4 v = ((const float4*)in)[i];
    __half2 h0 = __floats2half2_rn(v.x, v.y), h1 = __floats2half2_rn(v.z, v.w);
    float2 f0 = __half22float2(h0), f1 = __half22float2(h1);
    __half2 l0 = __floats2half2_rn(v.x - f0.x, v.y - f0.y);
    __half2 l1 = __floats2half2_rn(v.z - f1.x, v.w - f1.y);
    ((__half2*)hi)[2 * i] = h0; ((__half2*)hi)[2 * i + 1] = h1;
    ((__half2*)lo)[2 * i] = l0; ((__half2*)lo)[2 * i + 1] = l1;
}

// ---------------------------------------------------------------------------
// fp32 [R,C] -> transposed hi/lo fp16 [C,R] (weights only)
// ---------------------------------------------------------------------------
__global__ void __launch_bounds__(256)
transpose_convert_kernel(const float* __restrict__ in, __half* __restrict__ hi,
                         __half* __restrict__ lo, int R, int Cc)
{
    __shared__ float tb[32][33];
    const int c0 = blockIdx.x * 32;
    const int r0 = blockIdx.y * 32;
    const int x = threadIdx.x & 31;
    const int y = threadIdx.x >> 5;
#pragma unroll
    for (int j = 0; j < 32; j += 8)
        tb[y + j][x] = in[(long long)(r0 + y + j) * Cc + c0 + x];
    __syncthreads();
#pragma unroll
    for (int j = 0; j < 32; j += 8) {
        const float v = tb[x][y + j];
        const __half h = __float2half_rn(v);
        const __half l = __float2half_rn(v - __half2float(h));
        const long long o = (long long)(c0 + y + j) * R + r0 + x;
        hi[o] = h; lo[o] = l;
    }
}

// ---------------------------------------------------------------------------
// Row softmax over 2048 cols, fp32 in -> hi-only fp16 out.
// Contiguous per-thread mapping (thread t owns [t*8, t*8+8)).
// ---------------------------------------------------------------------------
__global__ void __launch_bounds__(256)
softmax_hi_kernel(const float* __restrict__ in, __half* __restrict__ hi, int cols)
{
    const long long row = blockIdx.x;
    const float* p = in + row * (long long)cols;
    const int t = threadIdx.x;

    float v[8];
    {
        float4 a = *(const float4*)(p + t * 8);
        float4 b = *(const float4*)(p + t * 8 + 4);
        v[0] = a.x; v[1] = a.y; v[2] = a.z; v[3] = a.w;
        v[4] = b.x; v[5] = b.y; v[6] = b.z; v[7] = b.w;
    }
    float vmax = -3.4e38f;
#pragma unroll
    for (int i = 0; i < 8; i++) vmax = fmaxf(vmax, v[i]);

    __shared__ float red[256];
    red[t] = vmax;
    __syncthreads();
#pragma unroll
    for (int s = 128; s > 0; s >>= 1) {
        if (t < s) red[t] = fmaxf(red[t], red[t + s]);
        __syncthreads();
    }
    vmax = red[0];
    __syncthreads();

    float sum = 0.0f;
#pragma unroll
    for (int i = 0; i < 8; i++) {
        v[i] = __expf(v[i] - vmax);
        sum += v[i];
    }
    red[t] = sum;
    __syncthreads();
#pragma unroll
    for (int s = 128; s > 0; s >>= 1) {
        if (t < s) red[t] += red[t + s];
        __syncthreads();
    }
    const float inv = 1.0f / red[0];

    __half2* ph = (__half2*)(hi + row * (long long)cols + t * 8);
#pragma unroll
    for (int i = 0; i < 8; i += 2)
        ph[i >> 1] = __floats2half2_rn(v[i] * inv, v[i + 1] * inv);
}

// ---------------------------------------------------------------------------
extern "C" void kernel_launch(void* const* d_in, const int* in_sizes, int n_in,
                              void* d_out, int out_size)
{
    const float* query  = (const float*)d_in[0];
    const float* keys   = (const float*)d_in[1];
    const float* values = (const float*)d_in[2];
    const float* Wq = (const float*)d_in[3];
    const float* bq = (const float*)d_in[4];
    const float* Wk = (const float*)d_in[5];
    const float* bk = (const float*)d_in[6];
    const float* Wv = (const float*)d_in[7];
    const float* bv = (const float*)d_in[8];
    const float* Wd = (const float*)d_in[9];
    const float* bd = (const float*)d_in[10];
    float* out = (float*)d_out;

    __half *inq_h, *inq_l, *ink_h, *ink_l, *inv_h, *inv_l;
    __half *wq_h, *wq_l, *wk_h, *wk_l, *wv_h, *wv_l, *wd_h, *wd_l;
    __half *q_h, *q_l, *k_h, *k_l, *vt_h, *s_h, *att_h;
    float *s;
    cudaGetSymbolAddress((void**)&inq_h, g_inq_h); cudaGetSymbolAddress((void**)&inq_l, g_inq_l);
    cudaGetSymbolAddress((void**)&ink_h, g_ink_h); cudaGetSymbolAddress((void**)&ink_l, g_ink_l);
    cudaGetSymbolAddress((void**)&inv_h, g_inv_h); cudaGetSymbolAddress((void**)&inv_l, g_inv_l);
    cudaGetSymbolAddress((void**)&wq_h, g_wq_h); cudaGetSymbolAddress((void**)&wq_l, g_wq_l);
    cudaGetSymbolAddress((void**)&wk_h, g_wk_h); cudaGetSymbolAddress((void**)&wk_l, g_wk_l);
    cudaGetSymbolAddress((void**)&wv_h, g_wv_h); cudaGetSymbolAddress((void**)&wv_l, g_wv_l);
    cudaGetSymbolAddress((void**)&wd_h, g_wd_h); cudaGetSymbolAddress((void**)&wd_l, g_wd_l);
    cudaGetSymbolAddress((void**)&q_h, g_q_h);   cudaGetSymbolAddress((void**)&q_l, g_q_l);
    cudaGetSymbolAddress((void**)&k_h, g_k_h);   cudaGetSymbolAddress((void**)&k_l, g_k_l);
    cudaGetSymbolAddress((void**)&vt_h, g_vt_h);
    cudaGetSymbolAddress((void**)&s_h, g_s_h);
    cudaGetSymbolAddress((void**)&att_h, g_att_h);
    cudaGetSymbolAddress((void**)&s, g_s);

    const int smem3 = 3 * 4 * 8192;   // 98304 (NPROD=3, 3-stage)
    const int smem1 = 4 * 2 * 8192;   // 65536 (NPROD=1, 4-stage)
    cudaFuncSetAttribute(hgemm_qk_kernel,           cudaFuncAttributeMaxDynamicSharedMemorySize, smem3);
    cudaFuncSetAttribute(hgemm_kernel<2, 2, 3, 3>,  cudaFuncAttributeMaxDynamicSharedMemorySize, smem3);
    cudaFuncSetAttribute(hgemm_kernel<0, 0, 3, 3>,  cudaFuncAttributeMaxDynamicSharedMemorySize, smem3);
    cudaFuncSetAttribute(hgemm_kernel<2, 0, 1, 4>,  cudaFuncAttributeMaxDynamicSharedMemorySize, smem1);
    cudaFuncSetAttribute(hgemm_kernel<0, 1, 1, 4>,  cudaFuncAttributeMaxDynamicSharedMemorySize, smem1);

    const long long strideQKV = (long long)SS * DD;
    const long long strideS   = (long long)SS * SS;

    dim3 tb(256);
    const size_t n4 = (size_t)MM * DD / 4;
    const int grc = (int)((n4 + 255) / 256);
    dim3 gt(DD / 32, DD / 32, 1);

    // [0..1] convert q,k inputs
    convert_kernel<<<grc, tb>>>(query,  inq_h, inq_l, n4);
    convert_kernel<<<grc, tb>>>(keys,   ink_h, ink_l, n4);
    // [2..3] transpose Wq, Wk
    transpose_convert_kernel<<<gt, tb>>>(Wq, wq_h, wq_l, DD, DD);
    transpose_convert_kernel<<<gt, tb>>>(Wk, wk_h, wk_l, DD, DD);
    // [4] convert values
    convert_kernel<<<grc, tb>>>(values, inv_h, inv_l, n4);

    // [5] q,k projections fused (z=2) -> hi/lo planes
    {
        QKArgs a;
        a.Ah[0] = inq_h; a.Al[0] = inq_l; a.Bh[0] = wq_h; a.Bl[0] = wq_l;
        a.bias[0] = bq;  a.Ch[0] = q_h;   a.Cl[0] = q_l;
        a.Ah[1] = ink_h; a.Al[1] = ink_l; a.Bh[1] = wk_h; a.Bl[1] = wk_l;
        a.bias[1] = bk;  a.Ch[1] = k_h;   a.Cl[1] = k_l;
        dim3 gqk(DD / 128, MM / 128, 2);
        hgemm_qk_kernel<<<gqk, tb, smem3>>>(a, MM, DD, DD);
    }

    // [6..7] transpose Wv, Wd
    transpose_convert_kernel<<<gt, tb>>>(Wv, wv_h, wv_l, DD, DD);
    transpose_convert_kernel<<<gt, tb>>>(Wd, wd_h, wd_l, DD, DD);

    // [8] vt[b][d][s] = (values @ Wv + bv)^T directly as GEMM (row bias),
    //     hi-only output (vt_lo is dead: consumer runs NPROD=1)
    {
        dim3 gv(SS / 128, DD / 128, BB);
        hgemm_kernel<2, 2, 3, 3><<<gv, tb, smem3>>>(wv_h, wv_l, inv_h, inv_l, bv,
                                                    nullptr, vt_h, nullptr,
                                                    DD, SS, DD,
                                                    0, strideQKV, strideQKV);
    }

    // [9] scores = q @ k^T per batch -> fp32 (full 3x split: precision-critical)
    {
        dim3 gg(SS / 128, SS / 128, BB);
        hgemm_kernel<0, 0, 3, 3><<<gg, tb, smem3>>>(q_h, q_l, k_h, k_l, nullptr,
                                                    s, nullptr, nullptr,
                                                    SS, SS, DD,
                                                    strideQKV, strideQKV, strideS);
    }

    // [10] softmax -> hi plane only
    softmax_hi_kernel<<<BB * SS, tb>>>(s, s_h, SS);

    // [11] attended = attn @ v -> hi only (1-product: s_h * vt_h)
    {
        dim3 gg(DD / 128, SS / 128, BB);
        hgemm_kernel<2, 0, 1, 4><<<gg, tb, smem1>>>(s_h, nullptr, vt_h, nullptr, nullptr,
                                                    nullptr, att_h, nullptr,
                                                    SS, DD, SS,
                                                    strideS, strideQKV, strideQKV);
    }

    // [12] out = attended @ Wd + bd -> fp32 (1-product: att_h * wd_h)
    {
        dim3 gg(DD / 128, MM / 128, 1);
        hgemm_kernel<0, 1, 1, 4><<<gg, tb, smem1>>>(att_h, nullptr, wd_h, nullptr, bd,
                                                    out, nullptr, nullptr, MM, DD, DD, 0, 0, 0);
    }
}

// round 17
// speedup vs baseline: 1.4610x; 1.4610x over previous
#include <cuda_runtime.h>
#include <cuda_fp16.h>
#include <cstdint>

#define BB 4
#define SS 2048
#define DD 1024
#define MM (BB * SS)

// ---------------- scratch (device globals; allocation-free) ----------------
__device__ __half g_inq_h[(size_t)MM * DD], g_inq_l[(size_t)MM * DD];
__device__ __half g_ink_h[(size_t)MM * DD], g_ink_l[(size_t)MM * DD];
__device__ __half g_inv_h[(size_t)MM * DD], g_inv_l[(size_t)MM * DD];
__device__ __half g_wq_h[(size_t)DD * DD],  g_wq_l[(size_t)DD * DD];
__device__ __half g_wk_h[(size_t)DD * DD],  g_wk_l[(size_t)DD * DD];
__device__ __half g_wv_h[(size_t)DD * DD],  g_wv_l[(size_t)DD * DD];
__device__ __half g_wd_h[(size_t)DD * DD],  g_wd_l[(size_t)DD * DD];
__device__ __half g_q_h[(size_t)MM * DD],   g_q_l[(size_t)MM * DD];
__device__ __half g_k_h[(size_t)MM * DD],   g_k_l[(size_t)MM * DD];
__device__ __half g_vt_h[(size_t)MM * DD];
__device__ __half g_s_h[(size_t)BB * SS * SS];
__device__ __half g_att_h[(size_t)MM * DD];
__device__ float g_s[(size_t)BB * SS * SS];

// ---------------- asm helpers ----------------
#define MMA16816(d, a, b) \
    asm volatile("mma.sync.aligned.m16n8k16.row.col.f32.f16.f16.f32 " \
                 "{%0,%1,%2,%3}, {%4,%5,%6,%7}, {%8,%9}, {%0,%1,%2,%3};" \
                 : "+f"((d)[0]), "+f"((d)[1]), "+f"((d)[2]), "+f"((d)[3]) \
                 : "r"((a)[0]), "r"((a)[1]), "r"((a)[2]), "r"((a)[3]), \
                   "r"((b)[0]), "r"((b)[1]))

#define LDSM4(r0, r1, r2, r3, addr) \
    asm volatile("ldmatrix.sync.aligned.m8n8.x4.shared.b16 {%0,%1,%2,%3}, [%4];" \
                 : "=r"(r0), "=r"(r1), "=r"(r2), "=r"(r3) : "r"(addr))

#define CPA16(dst, src) \
    asm volatile("cp.async.cg.shared.global [%0], [%1], 16;" \
                 :: "r"(dst), "l"(src) : "memory")
#define CPA_COMMIT() asm volatile("cp.async.commit_group;" ::: "memory")

template <int N>
__device__ __forceinline__ void cpa_wait() {
    asm volatile("cp.async.wait_group %0;" :: "n"(N) : "memory");
}

__device__ __forceinline__ uint32_t smem_u32(const void* p) {
    uint32_t a;
    asm("{ .reg .u64 t; cvta.to.shared.u64 t, %1; cvt.u32.u64 %0, t; }"
        : "=r"(a) : "l"(p));
    return a;
}
__device__ __forceinline__ uint32_t sw_addr(uint32_t plane, int row, int c) {
    return plane + (uint32_t)((row * 4 + (c ^ ((row >> 1) & 3))) * 16);
}

// ---------------------------------------------------------------------------
// fp16-split tensor GEMM body (pre-split hi/lo operand planes).
// 128x128x32 tile, 256 threads (8 warps 2x4, warp tile 64x32),
// cp.async NSTAGE-deep pipeline, ldmatrix.  [2 CTAs/SM]
// NPROD==3: C += Ah*Bh + Ah*Bl + Al*Bh   (planes: Ah,Al,Bh,Bl)
// NPROD==2: C += Ah*Bh + Ah*Bl           (planes: Ah,Bh,Bl)
// NPROD==1: C += Ah*Bh                   (planes: Ah,Bh)
// OMODE 0: fp32 out. OMODE 1: hi+lo fp16 out. OMODE 2: hi-only fp16 out.
// BMODE 0: none. 1: bias per column (bias[n]). 2: bias per row (bias[m]).
// ---------------------------------------------------------------------------
template <int OMODE, int BMODE, int NPROD, int NSTAGE>
__device__ __forceinline__ void
hgemm_body(const __half* __restrict__ Ahi, const __half* __restrict__ Alo,
           const __half* __restrict__ Bhi, const __half* __restrict__ Blo,
           const float* __restrict__ bias,
           float* __restrict__ Cf, __half* __restrict__ Chi, __half* __restrict__ Clo,
           int M, int N, int K, char* smem)
{
    constexpr int PLANE   = 8192;                    // 128 rows * 64B
    constexpr int NPLANES = (NPROD == 3) ? 4 : ((NPROD == 2) ? 3 : 2);
    constexpr int STAGE   = NPLANES * PLANE;
    const uint32_t sbase  = smem_u32(smem);

    const int bm = blockIdx.y * 128;
    const int bn = blockIdx.x * 128;
    const int t    = threadIdx.x;
    const int lane = t & 31;
    const int wid  = t >> 5;
    const int widM = wid & 1;
    const int widN = wid >> 1;
    const int g  = lane >> 2;
    const int qq = lane & 3;
    const int l7   = lane & 7;
    const int lsel = (lane >> 3) & 1;
    const int lch  = lane >> 4;

    const int cr = t >> 2;    // 0..63
    const int cc = t & 3;     // 16B chunk in 64B row

    const __half* srcb[NPLANES];
    if (NPROD == 3) {
        srcb[0] = Ahi + (long long)bm * K;
        srcb[1] = Alo + (long long)bm * K;
        srcb[2] = Bhi + (long long)bn * K;
        srcb[3] = Blo + (long long)bn * K;
    } else if (NPROD == 2) {
        srcb[0] = Ahi + (long long)bm * K;
        srcb[1] = Bhi + (long long)bn * K;
        srcb[2] = Blo + (long long)bn * K;
    } else {
        srcb[0] = Ahi + (long long)bm * K;
        srcb[1] = Bhi + (long long)bn * K;
    }

    auto issue = [&](int kt, int slot) {
        const uint32_t dstb = sbase + (uint32_t)slot * STAGE;
        const long long koff = (long long)kt * 32 + cc * 8;
#pragma unroll
        for (int i = 0; i < 2 * NPLANES; ++i) {
            const int p = i >> 1;
            const int r = (i & 1) * 64 + cr;
            CPA16(sw_addr(dstb + p * PLANE, r, cc), srcb[p] + (long long)r * K + koff);
        }
    };

    float acc[4][4][4];
#pragma unroll
    for (int i = 0; i < 4; i++)
#pragma unroll
        for (int j = 0; j < 4; j++)
#pragma unroll
            for (int r = 0; r < 4; r++) acc[i][j][r] = 0.0f;

    const int nIter = K >> 5;
    const int m0 = widM * 64;
    const int n0 = widN * 32;

#pragma unroll
    for (int pre = 0; pre < NSTAGE - 1; ++pre) {
        issue(pre, pre);
        CPA_COMMIT();
    }

    for (int it = 0; it < nIter; ++it) {
        cpa_wait<NSTAGE - 2>();
        __syncthreads();
        if (it + NSTAGE - 1 < nIter) issue(it + NSTAGE - 1, (it + NSTAGE - 1) % NSTAGE);
        CPA_COMMIT();

        const uint32_t stb  = sbase + (uint32_t)(it % NSTAGE) * STAGE;
        const uint32_t pAhi = stb;
        const uint32_t pAlo = (NPROD == 3) ? stb + PLANE : 0;
        const uint32_t pBhi = stb + (NPROD == 3 ? 2 : 1) * PLANE;
        const uint32_t pBlo = (NPROD >= 2) ? stb + (NPROD == 3 ? 3 : 2) * PLANE : 0;

#pragma unroll
        for (int kk = 0; kk < 2; ++kk) {
            const int c = 2 * kk + lch;
            uint32_t bh[4][2], bl[4][2];
#pragma unroll
            for (int np = 0; np < 2; ++np) {
                const int row = n0 + np * 16 + l7 + lsel * 8;
                uint32_t r0, r1, r2, r3;
                LDSM4(r0, r1, r2, r3, sw_addr(pBhi, row, c));
                bh[np * 2][0] = r0; bh[np * 2][1] = r2;
                bh[np * 2 + 1][0] = r1; bh[np * 2 + 1][1] = r3;
                if (NPROD >= 2) {
                    LDSM4(r0, r1, r2, r3, sw_addr(pBlo, row, c));
                    bl[np * 2][0] = r0; bl[np * 2][1] = r2;
                    bl[np * 2 + 1][0] = r1; bl[np * 2 + 1][1] = r3;
                }
            }
#pragma unroll
            for (int mt = 0; mt < 4; ++mt) {
                const int row = m0 + mt * 16 + l7 + lsel * 8;
                uint32_t ah[4], al[4];
                LDSM4(ah[0], ah[1], ah[2], ah[3], sw_addr(pAhi, row, c));
                if (NPROD == 3)
                    LDSM4(al[0], al[1], al[2], al[3], sw_addr(pAlo, row, c));
#pragma unroll
                for (int nt = 0; nt < 4; ++nt) {
                    MMA16816(acc[mt][nt], ah, bh[nt]);
                    if (NPROD >= 2) MMA16816(acc[mt][nt], ah, bl[nt]);
                    if (NPROD == 3) MMA16816(acc[mt][nt], al, bh[nt]);
                }
            }
        }
    }

    // ---- epilogue ----
#pragma unroll
    for (int nt = 0; nt < 4; ++nt) {
        const int col = bn + n0 + nt * 8 + 2 * qq;
        float b0 = 0.f, b1 = 0.f;
        if (BMODE == 1) { b0 = bias[col]; b1 = bias[col + 1]; }
#pragma unroll
        for (int mt = 0; mt < 4; ++mt) {
            const int row0 = bm + m0 + mt * 16 + g;
            float r0b = b0, r1b = b1, r2b = b0, r3b = b1;
            if (BMODE == 2) {
                const float brow0 = bias[row0];
                const float brow1 = bias[row0 + 8];
                r0b = brow0; r1b = brow0; r2b = brow1; r3b = brow1;
            }
            const float v0 = acc[mt][nt][0] + r0b, v1 = acc[mt][nt][1] + r1b;
            const float v2 = acc[mt][nt][2] + r2b, v3 = acc[mt][nt][3] + r3b;
            if (OMODE == 0) {
                *(float2*)(Cf + (long long)row0 * N + col)       = make_float2(v0, v1);
                *(float2*)(Cf + (long long)(row0 + 8) * N + col) = make_float2(v2, v3);
            } else {
                __half2 h0 = __floats2half2_rn(v0, v1);
                __half2 h1 = __floats2half2_rn(v2, v3);
                *(__half2*)(Chi + (long long)row0 * N + col)       = h0;
                *(__half2*)(Chi + (long long)(row0 + 8) * N + col) = h1;
                if (OMODE == 1) {
                    float2 f0 = __half22float2(h0);
                    float2 f1 = __half22float2(h1);
                    __half2 l0 = __floats2half2_rn(v0 - f0.x, v1 - f0.y);
                    __half2 l1 = __floats2half2_rn(v2 - f1.x, v3 - f1.y);
                    *(__half2*)(Clo + (long long)row0 * N + col)       = l0;
                    *(__half2*)(Clo + (long long)(row0 + 8) * N + col) = l1;
                }
            }
        }
    }
}

// Generic wrapper: batch offsets via blockIdx.z (sA=0 shares A across batches)
template <int OMODE, int BMODE, int NPROD, int NSTAGE>
__global__ void __launch_bounds__(256, 2)
hgemm_kernel(const __half* __restrict__ Ahi, const __half* __restrict__ Alo,
             const __half* __restrict__ Bhi, const __half* __restrict__ Blo,
             const float* __restrict__ bias,
             float* __restrict__ Cf, __half* __restrict__ Chi, __half* __restrict__ Clo,
             int M, int N, int K,
             long long sA, long long sB, long long sC)
{
    extern __shared__ char smem[];
    const long long zo = (long long)blockIdx.z;
    hgemm_body<OMODE, BMODE, NPROD, NSTAGE>(
        Ahi + zo * sA, (NPROD == 3) ? Alo + zo * sA : nullptr,
        Bhi + zo * sB, (NPROD >= 2) ? Blo + zo * sB : nullptr,
        bias,
        (OMODE == 0) ? Cf + zo * sC : nullptr,
        (OMODE != 0) ? Chi + zo * sC : nullptr,
        (OMODE == 1) ? Clo + zo * sC : nullptr,
        M, N, K, smem);
}

// Fused q/k projection: blockIdx.z selects operand set (wave packing)
struct QKArgs {
    const __half *Ah[2], *Al[2], *Bh[2], *Bl[2];
    const float* bias[2];
    __half *Ch[2], *Cl[2];
};
__global__ void __launch_bounds__(256, 2)
hgemm_qk_kernel(QKArgs a, int M, int N, int K)
{
    extern __shared__ char smem[];
    const int z = blockIdx.z;
    hgemm_body<1, 1, 3, 3>(a.Ah[z], a.Al[z], a.Bh[z], a.Bl[z], a.bias[z],
                           nullptr, a.Ch[z], a.Cl[z], M, N, K, smem);
}

// ---------------------------------------------------------------------------
// Fused fp32 -> hi/lo fp16 planes for 3 inputs (blockIdx.z selects tensor)
// ---------------------------------------------------------------------------
struct CvtArgs {
    const float* in[3];
    __half *hi[3], *lo[3];
};
__global__ void __launch_bounds__(256)
convert3_kernel(CvtArgs a, size_t n4)
{
    const int z = blockIdx.z;
    const float* in = a.in[z];
    __half* hi = a.hi[z];
    __half* lo = a.lo[z];
    size_t i = (size_t)blockIdx.x * blockDim.x + threadIdx.x;
    if (i >= n4) return;
    float4 v = ((const float4*)in)[i];
    __half2 h0 = __floats2half2_rn(v.x, v.y), h1 = __floats2half2_rn(v.z, v.w);
    float2 f0 = __half22float2(h0), f1 = __half22float2(h1);
    __half2 l0 = __floats2half2_rn(v.x - f0.x, v.y - f0.y);
    __half2 l1 = __floats2half2_rn(v.z - f1.x, v.w - f1.y);
    ((__half2*)hi)[2 * i] = h0; ((__half2*)hi)[2 * i + 1] = h1;
    ((__half2*)lo)[2 * i] = l0; ((__half2*)lo)[2 * i + 1] = l1;
}

// ---------------------------------------------------------------------------
// Fused weight transpose+convert for 4 weights (blockIdx.z selects tensor)
// fp32 [R,C] -> transposed hi/lo fp16 [C,R]
// ---------------------------------------------------------------------------
struct TrArgs {
    const float* in[4];
    __half *hi[4], *lo[4];
};
__global__ void __launch_bounds__(256)
transpose4_kernel(TrArgs a, int R, int Cc)
{
    __shared__ float tb[32][33];
    const int z = blockIdx.z;
    const float* in = a.in[z];
    __half* hi = a.hi[z];
    __half* lo = a.lo[z];
    const int c0 = blockIdx.x * 32;
    const int r0 = blockIdx.y * 32;
    const int x = threadIdx.x & 31;
    const int y = threadIdx.x >> 5;
#pragma unroll
    for (int j = 0; j < 32; j += 8)
        tb[y + j][x] = in[(long long)(r0 + y + j) * Cc + c0 + x];
    __syncthreads();
#pragma unroll
    for (int j = 0; j < 32; j += 8) {
        const float v = tb[x][y + j];
        const __half h = __float2half_rn(v);
        const __half l = __float2half_rn(v - __half2float(h));
        const long long o = (long long)(c0 + y + j) * R + r0 + x;
        hi[o] = h; lo[o] = l;
    }
}

// ---------------------------------------------------------------------------
// Row softmax over 2048 cols, fp32 in -> hi-only fp16 out.
// Contiguous per-thread mapping (thread t owns [t*8, t*8+8)).
// ---------------------------------------------------------------------------
__global__ void __launch_bounds__(256)
softmax_hi_kernel(const float* __restrict__ in, __half* __restrict__ hi, int cols)
{
    const long long row = blockIdx.x;
    const float* p = in + row * (long long)cols;
    const int t = threadIdx.x;

    float v[8];
    {
        float4 a = *(const float4*)(p + t * 8);
        float4 b = *(const float4*)(p + t * 8 + 4);
        v[0] = a.x; v[1] = a.y; v[2] = a.z; v[3] = a.w;
        v[4] = b.x; v[5] = b.y; v[6] = b.z; v[7] = b.w;
    }
    float vmax = -3.4e38f;
#pragma unroll
    for (int i = 0; i < 8; i++) vmax = fmaxf(vmax, v[i]);

    __shared__ float red[256];
    red[t] = vmax;
    __syncthreads();
#pragma unroll
    for (int s = 128; s > 0; s >>= 1) {
        if (t < s) red[t] = fmaxf(red[t], red[t + s]);
        __syncthreads();
    }
    vmax = red[0];
    __syncthreads();

    float sum = 0.0f;
#pragma unroll
    for (int i = 0; i < 8; i++) {
        v[i] = __expf(v[i] - vmax);
        sum += v[i];
    }
    red[t] = sum;
    __syncthreads();
#pragma unroll
    for (int s = 128; s > 0; s >>= 1) {
        if (t < s) red[t] += red[t + s];
        __syncthreads();
    }
    const float inv = 1.0f / red[0];

    __half2* ph = (__half2*)(hi + row * (long long)cols + t * 8);
#pragma unroll
    for (int i = 0; i < 8; i += 2)
        ph[i >> 1] = __floats2half2_rn(v[i] * inv, v[i + 1] * inv);
}

// ---------------------------------------------------------------------------
extern "C" void kernel_launch(void* const* d_in, const int* in_sizes, int n_in,
                              void* d_out, int out_size)
{
    const float* query  = (const float*)d_in[0];
    const float* keys   = (const float*)d_in[1];
    const float* values = (const float*)d_in[2];
    const float* Wq = (const float*)d_in[3];
    const float* bq = (const float*)d_in[4];
    const float* Wk = (const float*)d_in[5];
    const float* bk = (const float*)d_in[6];
    const float* Wv = (const float*)d_in[7];
    const float* bv = (const float*)d_in[8];
    const float* Wd = (const float*)d_in[9];
    const float* bd = (const float*)d_in[10];
    float* out = (float*)d_out;

    __half *inq_h, *inq_l, *ink_h, *ink_l, *inv_h, *inv_l;
    __half *wq_h, *wq_l, *wk_h, *wk_l, *wv_h, *wv_l, *wd_h, *wd_l;
    __half *q_h, *q_l, *k_h, *k_l, *vt_h, *s_h, *att_h;
    float *s;
    cudaGetSymbolAddress((void**)&inq_h, g_inq_h); cudaGetSymbolAddress((void**)&inq_l, g_inq_l);
    cudaGetSymbolAddress((void**)&ink_h, g_ink_h); cudaGetSymbolAddress((void**)&ink_l, g_ink_l);
    cudaGetSymbolAddress((void**)&inv_h, g_inv_h); cudaGetSymbolAddress((void**)&inv_l, g_inv_l);
    cudaGetSymbolAddress((void**)&wq_h, g_wq_h); cudaGetSymbolAddress((void**)&wq_l, g_wq_l);
    cudaGetSymbolAddress((void**)&wk_h, g_wk_h); cudaGetSymbolAddress((void**)&wk_l, g_wk_l);
    cudaGetSymbolAddress((void**)&wv_h, g_wv_h); cudaGetSymbolAddress((void**)&wv_l, g_wv_l);
    cudaGetSymbolAddress((void**)&wd_h, g_wd_h); cudaGetSymbolAddress((void**)&wd_l, g_wd_l);
    cudaGetSymbolAddress((void**)&q_h, g_q_h);   cudaGetSymbolAddress((void**)&q_l, g_q_l);
    cudaGetSymbolAddress((void**)&k_h, g_k_h);   cudaGetSymbolAddress((void**)&k_l, g_k_l);
    cudaGetSymbolAddress((void**)&vt_h, g_vt_h);
    cudaGetSymbolAddress((void**)&s_h, g_s_h);
    cudaGetSymbolAddress((void**)&att_h, g_att_h);
    cudaGetSymbolAddress((void**)&s, g_s);

    const int smem3 = 3 * 4 * 8192;   // 98304 (NPROD=3, 3-stage)
    const int smem1 = 5 * 2 * 8192;   // 81920 (NPROD=1, 5-stage)
    cudaFuncSetAttribute(hgemm_qk_kernel,           cudaFuncAttributeMaxDynamicSharedMemorySize, smem3);
    cudaFuncSetAttribute(hgemm_kernel<2, 2, 3, 3>,  cudaFuncAttributeMaxDynamicSharedMemorySize, smem3);
    cudaFuncSetAttribute(hgemm_kernel<0, 0, 3, 3>,  cudaFuncAttributeMaxDynamicSharedMemorySize, smem3);
    cudaFuncSetAttribute(hgemm_kernel<2, 0, 1, 5>,  cudaFuncAttributeMaxDynamicSharedMemorySize, smem1);
    cudaFuncSetAttribute(hgemm_kernel<0, 1, 1, 5>,  cudaFuncAttributeMaxDynamicSharedMemorySize, smem1);

    const long long strideQKV = (long long)SS * DD;
    const long long strideS   = (long long)SS * SS;

    dim3 tb(256);
    const size_t n4 = (size_t)MM * DD / 4;
    const int grc = (int)((n4 + 255) / 256);

    // [0] fused convert of all 3 inputs (z selects tensor)
    {
        CvtArgs a;
        a.in[0] = query;  a.hi[0] = inq_h; a.lo[0] = inq_l;
        a.in[1] = keys;   a.hi[1] = ink_h; a.lo[1] = ink_l;
        a.in[2] = values; a.hi[2] = inv_h; a.lo[2] = inv_l;
        dim3 gc(grc, 1, 3);
        convert3_kernel<<<gc, tb>>>(a, n4);
    }
    // [1] fused transpose+convert of all 4 weights (z selects tensor)
    {
        TrArgs a;
        a.in[0] = Wq; a.hi[0] = wq_h; a.lo[0] = wq_l;
        a.in[1] = Wk; a.hi[1] = wk_h; a.lo[1] = wk_l;
        a.in[2] = Wv; a.hi[2] = wv_h; a.lo[2] = wv_l;
        a.in[3] = Wd; a.hi[3] = wd_h; a.lo[3] = wd_l;
        dim3 gt(DD / 32, DD / 32, 4);
        transpose4_kernel<<<gt, tb>>>(a, DD, DD);
    }

    // [2] q,k projections fused (z=2) -> hi/lo planes
    {
        QKArgs a;
        a.Ah[0] = inq_h; a.Al[0] = inq_l; a.Bh[0] = wq_h; a.Bl[0] = wq_l;
        a.bias[0] = bq;  a.Ch[0] = q_h;   a.Cl[0] = q_l;
        a.Ah[1] = ink_h; a.Al[1] = ink_l; a.Bh[1] = wk_h; a.Bl[1] = wk_l;
        a.bias[1] = bk;  a.Ch[1] = k_h;   a.Cl[1] = k_l;
        dim3 gqk(DD / 128, MM / 128, 2);
        hgemm_qk_kernel<<<gqk, tb, smem3>>>(a, MM, DD, DD);
    }

    // [3] vt[b][d][s] = (values @ Wv + bv)^T directly as GEMM (row bias),
    //     hi-only output (vt_lo dead: consumer runs NPROD=1)
    {
        dim3 gv(SS / 128, DD / 128, BB);
        hgemm_kernel<2, 2, 3, 3><<<gv, tb, smem3>>>(wv_h, wv_l, inv_h, inv_l, bv,
                                                    nullptr, vt_h, nullptr,
                                                    DD, SS, DD,
                                                    0, strideQKV, strideQKV);
    }

    // [4] scores = q @ k^T per batch -> fp32 (full 3x split: precision-critical)
    {
        dim3 gg(SS / 128, SS / 128, BB);
        hgemm_kernel<0, 0, 3, 3><<<gg, tb, smem3>>>(q_h, q_l, k_h, k_l, nullptr,
                                                    s, nullptr, nullptr,
                                                    SS, SS, DD,
                                                    strideQKV, strideQKV, strideS);
    }

    // [5] softmax -> hi plane only
    softmax_hi_kernel<<<BB * SS, tb>>>(s, s_h, SS);

    // [6] attended = attn @ v -> hi only (1-product, 5-stage)
    {
        dim3 gg(DD / 128, SS / 128, BB);
        hgemm_kernel<2, 0, 1, 5><<<gg, tb, smem1>>>(s_h, nullptr, vt_h, nullptr, nullptr,
                                                    nullptr, att_h, nullptr,
                                                    SS, DD, SS,
                                                    strideS, strideQKV, strideQKV);
    }

    // [7] out = attended @ Wd + bd -> fp32 (1-product, 5-stage)
    {
        dim3 gg(DD / 128, MM / 128, 1);
        hgemm_kernel<0, 1, 1, 5><<<gg, tb, smem1>>>(att_h, nullptr, wd_h, nullptr, bd,
                                                    out, nullptr, nullptr, MM, DD, DD, 0, 0, 0);
    }
}